// round 10
// baseline (speedup 1.0000x reference)
#include <cuda_runtime.h>
#include <cuda_bf16.h>
#include <math.h>
#include <float.h>
#include <stdint.h>

#define BB 4
#define NP 16384
#define SP 2048
#define C1P 128
#define C2P 256
#define HP 256
#define MROWS (BB * NP)          // 65536
#define K1P 384
#define BN_EPS 1e-5f

// ---------------- device scratch (no allocation allowed) ----------------
__device__ int   g_idx[MROWS * 3];
__device__ float g_wt[MROWS * 3];
__device__ float g_s1[HP], g_b1[HP], g_s2[HP], g_b2[HP];
// weights pre-split to bf16 hi/lo, stored K-MAJOR: [K][H]
__device__ __align__(16) __nv_bfloat16 g_w1h[K1P * HP], g_w1l[K1P * HP];
__device__ __align__(16) __nv_bfloat16 g_w2h[HP * HP],  g_w2l[HP * HP];

// ---------------- mma/ldmatrix/cp.async helpers (baseline PTX, sm_80+) ------
__device__ __forceinline__ void ldsm4(uint32_t& r0, uint32_t& r1, uint32_t& r2, uint32_t& r3,
                                      uint32_t addr) {
    asm volatile("ldmatrix.sync.aligned.m8n8.x4.shared.b16 {%0,%1,%2,%3}, [%4];"
                 : "=r"(r0), "=r"(r1), "=r"(r2), "=r"(r3) : "r"(addr));
}
__device__ __forceinline__ void ldsm4t(uint32_t& r0, uint32_t& r1, uint32_t& r2, uint32_t& r3,
                                       uint32_t addr) {
    asm volatile("ldmatrix.sync.aligned.m8n8.x4.trans.shared.b16 {%0,%1,%2,%3}, [%4];"
                 : "=r"(r0), "=r"(r1), "=r"(r2), "=r"(r3) : "r"(addr));
}
__device__ __forceinline__ void mma16816(float* c, const uint32_t* a, const uint32_t* b) {
    asm volatile("mma.sync.aligned.m16n8k16.row.col.f32.bf16.bf16.f32 "
                 "{%0,%1,%2,%3}, {%4,%5,%6,%7}, {%8,%9}, {%0,%1,%2,%3};"
                 : "+f"(c[0]), "+f"(c[1]), "+f"(c[2]), "+f"(c[3])
                 : "r"(a[0]), "r"(a[1]), "r"(a[2]), "r"(a[3]), "r"(b[0]), "r"(b[1]));
}
__device__ __forceinline__ void cp16(uint32_t daddr, const void* src) {
    asm volatile("cp.async.cg.shared.global [%0], [%1], 16;" :: "r"(daddr), "l"(src));
}
__device__ __forceinline__ void cp_commit() {
    asm volatile("cp.async.commit_group;" ::: "memory");
}
__device__ __forceinline__ void cp_wait0() {
    asm volatile("cp.async.wait_group 0;" ::: "memory");
}
__device__ __forceinline__ void split2(float x, float y, uint32_t& hp, uint32_t& lp) {
    __nv_bfloat16 hx = __float2bfloat16(x), hy = __float2bfloat16(y);
    __nv_bfloat16 lx = __float2bfloat16(x - __bfloat162float(hx));
    __nv_bfloat16 ly = __float2bfloat16(y - __bfloat162float(hy));
    hp = ((uint32_t)__bfloat16_as_ushort(hy) << 16) | __bfloat16_as_ushort(hx);
    lp = ((uint32_t)__bfloat16_as_ushort(ly) << 16) | __bfloat16_as_ushort(lx);
}

// ---------------- prep: BN fold + W -> bf16 hi/lo split (k-major) ----------
__global__ void prep_kernel(const float* __restrict__ W1, const float* __restrict__ W2,
                            const float* __restrict__ g1, const float* __restrict__ be1,
                            const float* __restrict__ rm1, const float* __restrict__ rv1,
                            const float* __restrict__ g2, const float* __restrict__ be2,
                            const float* __restrict__ rm2, const float* __restrict__ rv2) {
    int i = blockIdx.x * blockDim.x + threadIdx.x;
    if (i < HP) {
        float s = g1[i] * rsqrtf(rv1[i] + BN_EPS);
        g_s1[i] = s; g_b1[i] = be1[i] - rm1[i] * s;
        float s2 = g2[i] * rsqrtf(rv2[i] + BN_EPS);
        g_s2[i] = s2; g_b2[i] = be2[i] - rm2[i] * s2;
    }
    if (i < K1P * HP) {                       // i = k*HP + n
        int k = i >> 8, n = i & 255;
        float v = W1[n * K1P + k];
        __nv_bfloat16 h = __float2bfloat16(v);
        g_w1h[i] = h;
        g_w1l[i] = __float2bfloat16(v - __bfloat162float(h));
    }
    if (i < HP * HP) {
        int k = i >> 8, n = i & 255;
        float v = W2[n * HP + k];
        __nv_bfloat16 h = __float2bfloat16(v);
        g_w2h[i] = h;
        g_w2l[i] = __float2bfloat16(v - __bfloat162float(h));
    }
}

// ---------------- 3-NN search (float4 candidates, 2 queries/thread) --------
__global__ void knn3_kernel(const float* __restrict__ xyz1, const float* __restrict__ xyz2) {
    __shared__ float4 sq[SP];                 // (x, y, z, |p|^2) per candidate: 32 KB
    const int b = blockIdx.y;
    const float* q = xyz2 + (size_t)b * SP * 3;
    for (int i = threadIdx.x; i < SP; i += blockDim.x) {
        float x = q[i * 3 + 0], y = q[i * 3 + 1], z = q[i * 3 + 2];
        sq[i] = make_float4(x, y, z, x * x + y * y + z * z);
    }
    __syncthreads();

    const int nA = blockIdx.x * 512 + threadIdx.x;   // query A
    const int nB = nA + 256;                          // query B (same batch)
    const float* pA = xyz1 + ((size_t)b * NP + nA) * 3;
    const float* pB = xyz1 + ((size_t)b * NP + nB) * 3;
    const float pAx = pA[0], pAy = pA[1], pAz = pA[2];
    const float pBx = pB[0], pBy = pB[1], pBz = pB[2];
    const float pnA = pAx * pAx + pAy * pAy + pAz * pAz;
    const float pnB = pBx * pBx + pBy * pBy + pBz * pBz;
    const float aAx = -2.0f * pAx, aAy = -2.0f * pAy, aAz = -2.0f * pAz;
    const float aBx = -2.0f * pBx, aBy = -2.0f * pBy, aBz = -2.0f * pBz;

    float vA0 = FLT_MAX, vA1 = FLT_MAX, vA2 = FLT_MAX;
    int iA0 = 0, iA1 = 0, iA2 = 0;
    float vB0 = FLT_MAX, vB1 = FLT_MAX, vB2 = FLT_MAX;
    int iB0 = 0, iB1 = 0, iB2 = 0;

#pragma unroll 8
    for (int s = 0; s < SP; s++) {
        float4 c = sq[s];
        float tA = fmaf(aAx, c.x, c.w);
        float tB = fmaf(aBx, c.x, c.w);
        tA = fmaf(aAy, c.y, tA);
        tB = fmaf(aBy, c.y, tB);
        tA = fmaf(aAz, c.z, tA);
        tB = fmaf(aBz, c.z, tB);
        if (tA < vA2) {
            if (tA < vA1) {
                if (tA < vA0) {
                    vA2 = vA1; iA2 = iA1; vA1 = vA0; iA1 = iA0; vA0 = tA; iA0 = s;
                } else {
                    vA2 = vA1; iA2 = iA1; vA1 = tA; iA1 = s;
                }
            } else {
                vA2 = tA; iA2 = s;
            }
        }
        if (tB < vB2) {
            if (tB < vB1) {
                if (tB < vB0) {
                    vB2 = vB1; iB2 = iB1; vB1 = vB0; iB1 = iB0; vB0 = tB; iB0 = s;
                } else {
                    vB2 = vB1; iB2 = iB1; vB1 = tB; iB1 = s;
                }
            } else {
                vB2 = tB; iB2 = s;
            }
        }
    }

    {
        float d0 = fmaxf(sqrtf(fmaxf(vA0 + pnA, 0.0f)), 1e-10f);
        float d1 = fmaxf(sqrtf(fmaxf(vA1 + pnA, 0.0f)), 1e-10f);
        float d2 = fmaxf(sqrtf(fmaxf(vA2 + pnA, 0.0f)), 1e-10f);
        float w0 = 1.0f / d0, w1 = 1.0f / d1, w2 = 1.0f / d2;
        float inv = 1.0f / (w0 + w1 + w2);
        int base = (b * NP + nA) * 3;
        g_idx[base + 0] = iA0; g_idx[base + 1] = iA1; g_idx[base + 2] = iA2;
        g_wt[base + 0] = w0 * inv; g_wt[base + 1] = w1 * inv; g_wt[base + 2] = w2 * inv;
    }
    {
        float d0 = fmaxf(sqrtf(fmaxf(vB0 + pnB, 0.0f)), 1e-10f);
        float d1 = fmaxf(sqrtf(fmaxf(vB1 + pnB, 0.0f)), 1e-10f);
        float d2 = fmaxf(sqrtf(fmaxf(vB2 + pnB, 0.0f)), 1e-10f);
        float w0 = 1.0f / d0, w1 = 1.0f / d1, w2 = 1.0f / d2;
        float inv = 1.0f / (w0 + w1 + w2);
        int base = (b * NP + nB) * 3;
        g_idx[base + 0] = iB0; g_idx[base + 1] = iB1; g_idx[base + 2] = iB2;
        g_wt[base + 0] = w0 * inv; g_wt[base + 1] = w1 * inv; g_wt[base + 2] = w2 * inv;
    }
}

// ---------------- fused interp + 2-layer MLP (mma.sync bf16x3, cp.async) ----
// SMEM layout (bytes):
#define SM_S1 0
#define SM_B1 1024
#define SM_S2 2048
#define SM_B2 3072
#define SM_SI 4096
#define SM_SW 5632
// A chunk: 128 rows x 32 k bf16, row stride 40 bf16 = 80 B (conflict-free ldmatrix)
#define A_HI 7168
#define A_LO 17408
// W chunk buffers (double): each = HI(16896) + LO(16896), k-major 32x256, stride 528 B
#define WBUF0 27648
#define WBUF1 61440
#define W_LO_OFF 16896
// h: 128 rows x 256 k bf16, row stride 264 bf16 = 528 B
#define H_HI 95232
#define H_LO 162816
#define SMEM_BYTES 230400

// async-copy one 32-k W chunk (hi+lo) into a buffer pair
__device__ __forceinline__ void cpW(const __nv_bfloat16* __restrict__ gh,
                                    const __nv_bfloat16* __restrict__ gl,
                                    int kbase, uint32_t wbase, uint32_t sb, int tid) {
    const uint4* srch = (const uint4*)gh;
    const uint4* srcl = (const uint4*)gl;
#pragma unroll
    for (int e = tid; e < 1024; e += 256) {
        int r = e >> 5, q = e & 31;
        uint32_t off = (uint32_t)r * 528 + q * 16;
        int gi = (kbase + r) * 32 + q;
        cp16(sb + wbase + off, srch + gi);
        cp16(sb + wbase + W_LO_OFF + off, srcl + gi);
    }
    cp_commit();
}

__global__ void __launch_bounds__(256, 1)
mlp_kernel(const float* __restrict__ points1, const float* __restrict__ points2,
           float* __restrict__ out) {
    extern __shared__ char smem[];
    const int tid = threadIdx.x;
    const int lane = tid & 31, wid = tid >> 5;
    const int wm = wid & 1, wn = wid >> 1;          // warp grid 2(M) x 4(N), tile 64x64
    const int row0 = blockIdx.x * 128;
    const int b = blockIdx.x >> 7;                  // 128 tiles per batch
    const uint32_t sb = (uint32_t)__cvta_generic_to_shared(smem);

    float* s_s1 = (float*)(smem + SM_S1);
    float* s_b1 = (float*)(smem + SM_B1);
    float* s_s2 = (float*)(smem + SM_S2);
    float* s_b2 = (float*)(smem + SM_B2);
    int*   s_si = (int*)(smem + SM_SI);
    float* s_sw = (float*)(smem + SM_SW);

    for (int i = tid; i < HP; i += 256) {
        s_s1[i] = g_s1[i]; s_b1[i] = g_b1[i];
        s_s2[i] = g_s2[i]; s_b2[i] = g_b2[i];
    }
    for (int i = tid; i < 384; i += 256) {
        s_si[i] = g_idx[row0 * 3 + i];
        s_sw[i] = g_wt[row0 * 3 + i];
    }

    // ---- preload W1 chunk 0 (async) while we build A chunk 0
    cpW(g_w1h, g_w1l, 0, WBUF0, sb, tid);

    float acc[4][8][4];
#pragma unroll
    for (int mt = 0; mt < 4; mt++)
#pragma unroll
        for (int nt = 0; nt < 8; nt++)
#pragma unroll
            for (int j = 0; j < 4; j++) acc[mt][nt][j] = 0.0f;

    const int qmh = ((lane >> 3) & 1) * 8;          // ldmatrix quad selectors
    const int qkh = (lane >> 4) * 8;
    const int lrow = lane & 7;
    const int arow = tid >> 1, akh = (tid & 1) * 16;   // A-build assignment

    __syncthreads();                                   // s_si/s_sw visible for interp

    // helper-free A build: chunk kc -> hp/lp regs
    uint32_t ahp[8], alp[8];
    {
        // chunk 0 is always points1 (kg < 128)
        const float4* s4 = (const float4*)(points1 + (size_t)(row0 + arow) * C1P + akh);
#pragma unroll
        for (int qq = 0; qq < 4; qq++) {
            float4 f = s4[qq];
            split2(f.x, f.y, ahp[2 * qq], alp[2 * qq]);
            split2(f.z, f.w, ahp[2 * qq + 1], alp[2 * qq + 1]);
        }
#pragma unroll
        for (int i2 = 0; i2 < 8; i2++) {
            uint32_t off = arow * 80 + (akh + 2 * i2) * 2;
            *(uint32_t*)(smem + A_HI + off) = ahp[i2];
            *(uint32_t*)(smem + A_LO + off) = alp[i2];
        }
    }
    cp_wait0();
    __syncthreads();

    // ================= LAYER 1: K=384, 12 chunks of 32 =================
#pragma unroll 1
    for (int kc = 0; kc < 12; kc++) {
        const uint32_t wb = (kc & 1) ? WBUF1 : WBUF0;
        if (kc < 11) cpW(g_w1h, g_w1l, (kc + 1) * 32, (kc & 1) ? WBUF0 : WBUF1, sb, tid);

        // ---- MMA on chunk kc
#pragma unroll
        for (int kk = 0; kk < 2; kk++) {
            uint32_t bh[8][2], bl[8][2];
#pragma unroll
            for (int np = 0; np < 4; np++) {
                int n0 = wn * 64 + np * 16;
                uint32_t roff = (uint32_t)(kk * 16 + qmh + lrow) * 528 + (n0 + qkh) * 2;
                ldsm4t(bh[2 * np][0], bh[2 * np][1], bh[2 * np + 1][0], bh[2 * np + 1][1],
                       sb + wb + roff);
                ldsm4t(bl[2 * np][0], bl[2 * np][1], bl[2 * np + 1][0], bl[2 * np + 1][1],
                       sb + wb + W_LO_OFF + roff);
            }
#pragma unroll
            for (int mt = 0; mt < 4; mt++) {
                int m0 = wm * 64 + mt * 16;
                uint32_t aoff = (uint32_t)(m0 + qmh + lrow) * 80 + (kk * 16 + qkh) * 2;
                uint32_t ah[4], al[4];
                ldsm4(ah[0], ah[1], ah[2], ah[3], sb + A_HI + aoff);
                ldsm4(al[0], al[1], al[2], al[3], sb + A_LO + aoff);
#pragma unroll
                for (int nt = 0; nt < 8; nt++) {
                    mma16816(acc[mt][nt], ah, bh[nt]);
                    mma16816(acc[mt][nt], ah, bl[nt]);
                    mma16816(acc[mt][nt], al, bh[nt]);
                }
            }
        }

        // ---- build A chunk kc+1 into regs (overlaps MMA; LDGs independent)
        if (kc < 11) {
            const int kg = (kc + 1) * 32 + akh;
            if (kg < C1P) {
                const float4* s4 = (const float4*)(points1 + (size_t)(row0 + arow) * C1P + kg);
#pragma unroll
                for (int qq = 0; qq < 4; qq++) {
                    float4 f = s4[qq];
                    split2(f.x, f.y, ahp[2 * qq], alp[2 * qq]);
                    split2(f.z, f.w, ahp[2 * qq + 1], alp[2 * qq + 1]);
                }
            } else {
                const int c2 = kg - C1P;
                const float* p2 = points2 + (size_t)b * SP * C2P + c2;
                const int ib = arow * 3;
                const float w0 = s_sw[ib], w1 = s_sw[ib + 1], w2 = s_sw[ib + 2];
                const float4* q0 = (const float4*)(p2 + (size_t)s_si[ib] * C2P);
                const float4* q1 = (const float4*)(p2 + (size_t)s_si[ib + 1] * C2P);
                const float4* q2 = (const float4*)(p2 + (size_t)s_si[ib + 2] * C2P);
#pragma unroll
                for (int qq = 0; qq < 4; qq++) {
                    float4 f0 = q0[qq], f1 = q1[qq], f2 = q2[qq];
                    float vx = fmaf(w2, f2.x, fmaf(w1, f1.x, w0 * f0.x));
                    float vy = fmaf(w2, f2.y, fmaf(w1, f1.y, w0 * f0.y));
                    float vz = fmaf(w2, f2.z, fmaf(w1, f1.z, w0 * f0.z));
                    float vw = fmaf(w2, f2.w, fmaf(w1, f1.w, w0 * f0.w));
                    split2(vx, vy, ahp[2 * qq], alp[2 * qq]);
                    split2(vz, vw, ahp[2 * qq + 1], alp[2 * qq + 1]);
                }
            }
        }
        __syncthreads();                       // A[kc] ldmatrix reads complete
        if (kc < 11) {
#pragma unroll
            for (int i2 = 0; i2 < 8; i2++) {
                uint32_t off = arow * 80 + (akh + 2 * i2) * 2;
                *(uint32_t*)(smem + A_HI + off) = ahp[i2];
                *(uint32_t*)(smem + A_LO + off) = alp[i2];
            }
            cp_wait0();                        // W[kc+1] landed (own portion)
        }
        __syncthreads();                       // publish A stores + W buffer
    }

    // ---- prefetch W2 chunk 0 (overlaps epilogue-1); WBUF0's readers are done
    cpW(g_w2h, g_w2l, 0, WBUF0, sb, tid);

    // ================= EPILOGUE 1: BN+ReLU -> h (bf16 hi/lo, smem) =========
#pragma unroll
    for (int mt = 0; mt < 4; mt++)
#pragma unroll
    for (int nt = 0; nt < 8; nt++) {
        int m0 = wm * 64 + mt * 16, n0 = wn * 64 + nt * 8;
        int r0 = m0 + (lane >> 2), n = n0 + 2 * (lane & 3);
        float s0 = s_s1[n], s1v = s_s1[n + 1], b0v = s_b1[n], b1v = s_b1[n + 1];
        float* c = acc[mt][nt];
        float v0 = fmaxf(fmaf(c[0], s0, b0v), 0.0f);
        float v1 = fmaxf(fmaf(c[1], s1v, b1v), 0.0f);
        uint32_t hp, lp;
        split2(v0, v1, hp, lp);
        uint32_t off = r0 * 528 + n * 2;
        *(uint32_t*)(smem + H_HI + off) = hp;
        *(uint32_t*)(smem + H_LO + off) = lp;
        v0 = fmaxf(fmaf(c[2], s0, b0v), 0.0f);
        v1 = fmaxf(fmaf(c[3], s1v, b1v), 0.0f);
        split2(v0, v1, hp, lp);
        off = (r0 + 8) * 528 + n * 2;
        *(uint32_t*)(smem + H_HI + off) = hp;
        *(uint32_t*)(smem + H_LO + off) = lp;
    }

#pragma unroll
    for (int mt = 0; mt < 4; mt++)
#pragma unroll
        for (int nt = 0; nt < 8; nt++)
#pragma unroll
            for (int j = 0; j < 4; j++) acc[mt][nt][j] = 0.0f;

    // ================= LAYER 2: K=256, 8 chunks of 32 =================
#pragma unroll 1
    for (int kc = 0; kc < 8; kc++) {
        cp_wait0();                            // W2[kc] landed (own portion)
        __syncthreads();                       // publish W2[kc] (+ H on kc==0)
        const uint32_t wb = (kc & 1) ? WBUF1 : WBUF0;
        if (kc < 7) cpW(g_w2h, g_w2l, (kc + 1) * 32, (kc & 1) ? WBUF0 : WBUF1, sb, tid);
#pragma unroll
        for (int kk = 0; kk < 2; kk++) {
            uint32_t bh[8][2], bl[8][2];
#pragma unroll
            for (int np = 0; np < 4; np++) {
                int n0 = wn * 64 + np * 16;
                uint32_t roff = (uint32_t)(kk * 16 + qmh + lrow) * 528 + (n0 + qkh) * 2;
                ldsm4t(bh[2 * np][0], bh[2 * np][1], bh[2 * np + 1][0], bh[2 * np + 1][1],
                       sb + wb + roff);
                ldsm4t(bl[2 * np][0], bl[2 * np][1], bl[2 * np + 1][0], bl[2 * np + 1][1],
                       sb + wb + W_LO_OFF + roff);
            }
#pragma unroll
            for (int mt = 0; mt < 4; mt++) {
                int m0 = wm * 64 + mt * 16;
                uint32_t aoff = (uint32_t)(m0 + qmh + lrow) * 528 + (kc * 32 + kk * 16 + qkh) * 2;
                uint32_t ah[4], al[4];
                ldsm4(ah[0], ah[1], ah[2], ah[3], sb + H_HI + aoff);
                ldsm4(al[0], al[1], al[2], al[3], sb + H_LO + aoff);
#pragma unroll
                for (int nt = 0; nt < 8; nt++) {
                    mma16816(acc[mt][nt], ah, bh[nt]);
                    mma16816(acc[mt][nt], ah, bl[nt]);
                    mma16816(acc[mt][nt], al, bh[nt]);
                }
            }
        }
    }

    // ================= EPILOGUE 2: BN+ReLU -> fp32 out =================
#pragma unroll
    for (int mt = 0; mt < 4; mt++)
#pragma unroll
    for (int nt = 0; nt < 8; nt++) {
        int m0 = wm * 64 + mt * 16, n0 = wn * 64 + nt * 8;
        int r0 = m0 + (lane >> 2), n = n0 + 2 * (lane & 3);
        float s0 = s_s2[n], s1v = s_s2[n + 1], b0v = s_b2[n], b1v = s_b2[n + 1];
        float* c = acc[mt][nt];
        float2 o;
        o.x = fmaxf(fmaf(c[0], s0, b0v), 0.0f);
        o.y = fmaxf(fmaf(c[1], s1v, b1v), 0.0f);
        *(float2*)(out + (size_t)(row0 + r0) * HP + n) = o;
        o.x = fmaxf(fmaf(c[2], s0, b0v), 0.0f);
        o.y = fmaxf(fmaf(c[3], s1v, b1v), 0.0f);
        *(float2*)(out + (size_t)(row0 + r0 + 8) * HP + n) = o;
    }
}

// ---------------- launch ----------------
extern "C" void kernel_launch(void* const* d_in, const int* in_sizes, int n_in,
                              void* d_out, int out_size) {
    const float* xyz1    = (const float*)d_in[0];
    const float* xyz2    = (const float*)d_in[1];
    const float* points1 = (const float*)d_in[2];
    const float* points2 = (const float*)d_in[3];
    const float* W1      = (const float*)d_in[4];
    const float* gamma1  = (const float*)d_in[5];
    const float* beta1   = (const float*)d_in[6];
    const float* rm1     = (const float*)d_in[7];
    const float* rv1     = (const float*)d_in[8];
    const float* W2      = (const float*)d_in[9];
    const float* gamma2  = (const float*)d_in[10];
    const float* beta2   = (const float*)d_in[11];
    const float* rm2     = (const float*)d_in[12];
    const float* rv2     = (const float*)d_in[13];
    float* out = (float*)d_out;

    cudaFuncSetAttribute(mlp_kernel, cudaFuncAttributeMaxDynamicSharedMemorySize, SMEM_BYTES);

    prep_kernel<<<(K1P * HP + 255) / 256, 256>>>(W1, W2, gamma1, beta1, rm1, rv1,
                                                 gamma2, beta2, rm2, rv2);
    knn3_kernel<<<dim3(NP / 512, BB), 256>>>(xyz1, xyz2);
    mlp_kernel<<<MROWS / 128, 256, SMEM_BYTES>>>(points1, points2, out);
}